// round 1
// baseline (speedup 1.0000x reference)
#include <cuda_runtime.h>
#include <cuda_bf16.h>

// Problem constants (fixed by the reference: B=2,000,000, F=21, 7 classes,
// normal range (0, 1000) for the penalty column targets[:,1], class column
// targets[:,2] in {100..700}).
constexpr int   NF      = 21;
constexpr int   BTOT    = 2000000;
constexpr int   BDIM    = 256;                       // rows per block == threads per block
constexpr int   NBLOCKS = (BTOT + BDIM - 1) / BDIM;  // 7813 (last block: 128 rows)

// Deterministic scratch: every block writes its slot every launch, then the
// finalize kernel reads them. No zeroing, no atomics, no allocation.
__device__ double g_partials[2 * NBLOCKS];

__global__ void __launch_bounds__(BDIM) wmse_main(
    const float* __restrict__ in,
    const int*   __restrict__ tg,
    const float* __restrict__ w)
{
    __shared__ float s_in[BDIM * NF];   // 21504 B
    __shared__ int   s_tg[BDIM * NF];   // 21504 B
    __shared__ float s_w[7];
    __shared__ float r_acc[BDIM / 32];
    __shared__ float r_pen[BDIM / 32];

    const int tid  = threadIdx.x;
    const int bid  = blockIdx.x;
    const int r0   = bid * BDIM;
    const int rows = min(BDIM, BTOT - r0);           // 256, or 128 for the last block

    if (tid < 7) s_w[tid] = w[tid];

    // --- Stage 1: coalesced 16B global->shared copy -------------------------
    // Base byte offset = r0*NF*4 = bid*21504, which is 16B-aligned.
    const float4* gin4 = reinterpret_cast<const float4*>(in + (size_t)r0 * NF);
    const int4*   gtg4 = reinterpret_cast<const int4*>(tg + (size_t)r0 * NF);
    float4* si4 = reinterpret_cast<float4*>(s_in);
    int4*   st4 = reinterpret_cast<int4*>(s_tg);

    if (rows == BDIM) {
        // 256*21/4 = 1344 float4s = 5 full sweeps + 64-thread tail.
        #pragma unroll
        for (int j = 0; j < 5; j++) {
            const int k = tid + j * BDIM;
            si4[k] = gin4[k];
            st4[k] = gtg4[k];
        }
        {
            const int k = tid + 5 * BDIM;
            if (k < (BDIM * NF) / 4) { si4[k] = gin4[k]; st4[k] = gtg4[k]; }
        }
    } else {
        // Last block: rows=128 -> 128*21/4 = 672 vectors, still /4-exact.
        const int n4 = (rows * NF) / 4;
        for (int k = tid; k < n4; k += BDIM) { si4[k] = gin4[k]; st4[k] = gtg4[k]; }
    }
    __syncthreads();

    // --- Stage 2: one row per thread (stride-21 SMEM reads: conflict-free) --
    float acc = 0.0f;   // w[cls] * sum_f diff^2   (un-normalized)
    float pen = 0.0f;   // range penalty for this row
    if (tid < rows) {
        const float* ri = s_in + tid * NF;
        const int*   rt = s_tg + tid * NF;

        const int   cls = rt[2] / 100 - 1;           // {100..700} -> {0..6}
        const float wgt = s_w[cls];

        float s = 0.0f;
        #pragma unroll
        for (int f = 0; f < NF; f++) {
            const float d = ri[f] - (float)rt[f];
            s = fmaf(d, d, s);
        }
        acc = wgt * s;

        const float v = (float)rt[1];
        if (v < 0.0f)          pen = v * v;
        else if (v > 1000.0f)  { const float u = v - 1000.0f; pen = u * u; }
    }

    // --- Stage 3: block reduction (fp32 within warp, double across warps) ---
    #pragma unroll
    for (int off = 16; off > 0; off >>= 1) {
        acc += __shfl_down_sync(0xFFFFFFFFu, acc, off);
        pen += __shfl_down_sync(0xFFFFFFFFu, pen, off);
    }
    if ((tid & 31) == 0) { r_acc[tid >> 5] = acc; r_pen[tid >> 5] = pen; }
    __syncthreads();
    if (tid == 0) {
        double a = 0.0, p = 0.0;
        #pragma unroll
        for (int i = 0; i < BDIM / 32; i++) { a += (double)r_acc[i]; p += (double)r_pen[i]; }
        g_partials[bid]           = a;
        g_partials[NBLOCKS + bid] = p;
    }
}

__global__ void __launch_bounds__(1024) wmse_final(float* __restrict__ out)
{
    __shared__ double sa[32];
    __shared__ double sp[32];

    double a = 0.0, p = 0.0;
    for (int i = threadIdx.x; i < NBLOCKS; i += 1024) {
        a += g_partials[i];
        p += g_partials[NBLOCKS + i];
    }
    #pragma unroll
    for (int off = 16; off > 0; off >>= 1) {
        a += __shfl_down_sync(0xFFFFFFFFu, a, off);
        p += __shfl_down_sync(0xFFFFFFFFu, p, off);
    }
    const int wid = threadIdx.x >> 5;
    const int lane = threadIdx.x & 31;
    if (lane == 0) { sa[wid] = a; sp[wid] = p; }
    __syncthreads();
    if (wid == 0) {
        a = sa[lane];
        p = sp[lane];
        #pragma unroll
        for (int off = 16; off > 0; off >>= 1) {
            a += __shfl_down_sync(0xFFFFFFFFu, a, off);
            p += __shfl_down_sync(0xFFFFFFFFu, p, off);
        }
        if (lane == 0)
            out[0] = (float)(a / ((double)BTOT * (double)NF) + p);
    }
}

extern "C" void kernel_launch(void* const* d_in, const int* in_sizes, int n_in,
                              void* d_out, int out_size)
{
    const float* in = (const float*)d_in[0];   // inputs  [B, 21] f32
    const int*   tg = (const int*)d_in[1];     // targets [B, 21] i32
    const float* w  = (const float*)d_in[2];   // weights [7]     f32
    float*       out = (float*)d_out;          // scalar  f32

    wmse_main<<<NBLOCKS, BDIM>>>(in, tg, w);
    wmse_final<<<1, 1024>>>(out);
}

// round 2
// speedup vs baseline: 1.0336x; 1.0336x over previous
#include <cuda_runtime.h>
#include <cuda_bf16.h>

// Fixed problem shape: B=2,000,000 rows x F=21 cols, 7 classes (targets[:,2] in
// {100..700}), range penalty on targets[:,1] vs (0, 1000).
constexpr int NF    = 21;
constexpr int BTOT  = 2000000;
constexpr int GELEM = 32 * NF;            // 672 floats per 32-row group
constexpr int NVEC  = GELEM / 4;          // 168 float4 per group (exact)
constexpr int NGRP  = BTOT / 32;          // 62500 groups (exact)

constexpr int BDIM  = 256;
constexpr int WPB   = BDIM / 32;          // 8 warps/block
constexpr int NB    = 1184;               // 148 SMs * 8 blocks
constexpr int TOTW  = NB * WPB;           // 9472 warps grid-wide

__device__ double       g_pa[NB];
__device__ double       g_pp[NB];
__device__ unsigned int g_ctr = 0;        // reset by the finishing block each launch

__global__ void __launch_bounds__(BDIM) wmse_fused(
    const float* __restrict__ in,
    const int*   __restrict__ tg,
    const float* __restrict__ w,
    float*       __restrict__ out)
{
    const int lane = threadIdx.x & 31;
    const int wid  = threadIdx.x >> 5;
    const int gw   = blockIdx.x * WPB + wid;

    float acc = 0.0f;   // sum of w[cls_row] * diff^2 (un-normalized)
    float pen = 0.0f;   // range penalty sum

    for (int g = gw; g < NGRP; g += TOTW) {
        const size_t base = (size_t)g * GELEM;

        // Per-lane row metadata (same cache lines as the bulk loads -> no extra DRAM).
        const int row = g * 32 + lane;
        const int t1  = __ldg(&tg[(size_t)row * NF + 1]);
        const int t2  = __ldg(&tg[(size_t)row * NF + 2]);
        const float wl = __ldg(&w[t2 / 100 - 1]);     // this lane's row weight

        {
            const float v = (float)t1;
            if (v < 0.0f)         pen = fmaf(v, v, pen);
            else if (v > 1000.0f) { const float u = v - 1000.0f; pen = fmaf(u, u, pen); }
        }

        const float4* in4 = reinterpret_cast<const float4*>(in + base);
        const int4*   tg4 = reinterpret_cast<const int4*>(tg + base);

        // Front-batch all 12 vector loads (high MLP).
        float4 x[6];
        int4   t[6];
        #pragma unroll
        for (int k = 0; k < 5; k++) {
            x[k] = in4[k * 32 + lane];
            t[k] = tg4[k * 32 + lane];
        }
        x[5] = make_float4(0.f, 0.f, 0.f, 0.f);
        t[5] = make_int4(0, 0, 0, 0);
        if (lane < NVEC - 160) {                      // lanes 0..7 carry the tail
            x[5] = in4[160 + lane];
            t[5] = tg4[160 + lane];
        }

        #pragma unroll
        for (int k = 0; k < 6; k++) {
            const unsigned e0 = (unsigned)(k * 32 + lane) * 4u;
            const float xs[4] = {x[k].x, x[k].y, x[k].z, x[k].w};
            const int   ts[4] = {t[k].x, t[k].y, t[k].z, t[k].w};
            #pragma unroll
            for (int j = 0; j < 4; j++) {
                const unsigned e = e0 + j;
                const unsigned r = (e * 6243u) >> 17;          // e/21, exact for e<4228
                const float wr = __shfl_sync(0xFFFFFFFFu, wl, (int)(r & 31u));
                const float d  = xs[j] - (float)ts[j];          // tail lanes: 0-0 = 0
                acc = fmaf(wr * d, d, acc);
            }
        }
    }

    // ---- warp reduce (fp32), then double across warps ----------------------
    #pragma unroll
    for (int off = 16; off > 0; off >>= 1) {
        acc += __shfl_down_sync(0xFFFFFFFFu, acc, off);
        pen += __shfl_down_sync(0xFFFFFFFFu, pen, off);
    }

    __shared__ float sa[WPB], sp[WPB];
    __shared__ bool  s_last;
    if (lane == 0) { sa[wid] = acc; sp[wid] = pen; }
    __syncthreads();

    if (threadIdx.x == 0) {
        double a = 0.0, p = 0.0;
        #pragma unroll
        for (int i = 0; i < WPB; i++) { a += (double)sa[i]; p += (double)sp[i]; }
        g_pa[blockIdx.x] = a;
        g_pp[blockIdx.x] = p;
        __threadfence();
        const unsigned old = atomicAdd(&g_ctr, 1u);
        s_last = (old == (unsigned)(NB - 1));
    }
    __syncthreads();

    // ---- last-arriving block folds all partials (L2-resident) --------------
    if (s_last) {
        double a = 0.0, p = 0.0;
        for (int i = threadIdx.x; i < NB; i += BDIM) { a += g_pa[i]; p += g_pp[i]; }

        #pragma unroll
        for (int off = 16; off > 0; off >>= 1) {
            a += __shfl_down_sync(0xFFFFFFFFu, a, off);
            p += __shfl_down_sync(0xFFFFFFFFu, p, off);
        }
        __shared__ double da[WPB], dp[WPB];
        if (lane == 0) { da[wid] = a; dp[wid] = p; }
        __syncthreads();
        if (threadIdx.x == 0) {
            double fa = 0.0, fp = 0.0;
            #pragma unroll
            for (int i = 0; i < WPB; i++) { fa += da[i]; fp += dp[i]; }
            out[0] = (float)(fa / ((double)BTOT * (double)NF) + fp);
            g_ctr = 0;   // re-arm for next graph replay
        }
    }
}

extern "C" void kernel_launch(void* const* d_in, const int* in_sizes, int n_in,
                              void* d_out, int out_size)
{
    const float* in = (const float*)d_in[0];   // inputs  [B, 21] f32
    const int*   tg = (const int*)d_in[1];     // targets [B, 21] i32
    const float* w  = (const float*)d_in[2];   // weights [7]     f32
    float*       out = (float*)d_out;          // scalar  f32

    wmse_fused<<<NB, BDIM>>>(in, tg, w, out);
}

// round 3
// speedup vs baseline: 1.4819x; 1.4337x over previous
#include <cuda_runtime.h>
#include <cuda_bf16.h>

// Fixed shape: B=2,000,000 rows x F=21 cols, 7 classes (targets[:,2] in
// {100..700}), range penalty on targets[:,1] vs (0, 1000).
constexpr int NF    = 21;
constexpr int BTOT  = 2000000;
constexpr int GELEM = 32 * NF;            // 672 floats per 32-row group
constexpr int NVEC  = GELEM / 4;          // 168 float4 per group
constexpr int NGRP  = BTOT / 32;          // 62500 groups

constexpr int BDIM  = 256;
constexpr int WPB   = BDIM / 32;          // 8 warps/block
constexpr int NB    = 592;                // 148 SMs * 4 CTAs
constexpr int TOTW  = NB * WPB;           // 4736 warps grid-wide

__device__ double       g_pa[NB];
__device__ double       g_pp[NB];
__device__ unsigned int g_ctr = 0;        // re-armed by the finishing block

// Process one float4/int4 pair: the 4 elements span at most 2 rows.
// Split the unweighted squared-diff sum at the row boundary, then apply the
// two row weights with 2 shfls (vs 4 in the per-element scheme).
__device__ __forceinline__ void proc_vec(
    float4 xv, int4 tv, unsigned e0, float wl, float& acc)
{
    const unsigned r0  = (e0 * 6243u) >> 17;           // e0/21, exact here
    const unsigned rem = e0 - r0 * 21u;                // 0..20

    const float d0 = xv.x - (float)tv.x;
    const float d1 = xv.y - (float)tv.y;
    const float d2 = xv.z - (float)tv.z;
    const float d3 = xv.w - (float)tv.w;

    float s0 = 0.0f, s1 = 0.0f;
    if (rem + 0u < 21u) s0 = fmaf(d0, d0, s0); else s1 = fmaf(d0, d0, s1);
    if (rem + 1u < 21u) s0 = fmaf(d1, d1, s0); else s1 = fmaf(d1, d1, s1);
    if (rem + 2u < 21u) s0 = fmaf(d2, d2, s0); else s1 = fmaf(d2, d2, s1);
    if (rem + 3u < 21u) s0 = fmaf(d3, d3, s0); else s1 = fmaf(d3, d3, s1);

    const float w0 = __shfl_sync(0xFFFFFFFFu, wl, (int)(r0 & 31u));
    const float w1 = __shfl_sync(0xFFFFFFFFu, wl, (int)((r0 + 1u) & 31u));
    acc = fmaf(w0, s0, acc);
    acc = fmaf(w1, s1, acc);
}

__global__ void __launch_bounds__(BDIM, 4) wmse_fused(
    const float* __restrict__ in,
    const int*   __restrict__ tg,
    const float* __restrict__ w,
    float*       __restrict__ out)
{
    const int lane = threadIdx.x & 31;
    const int wid  = threadIdx.x >> 5;
    const int gw   = blockIdx.x * WPB + wid;

    float acc = 0.0f;   // sum of w[cls_row] * diff^2 (un-normalized)
    float pen = 0.0f;   // range penalty sum

    for (int g = gw; g < NGRP; g += TOTW) {
        const size_t base = (size_t)g * GELEM;

        // Per-lane row metadata (same cache lines as the bulk loads).
        const int row = g * 32 + lane;
        const int t1  = __ldg(&tg[(size_t)row * NF + 1]);
        const int t2  = __ldg(&tg[(size_t)row * NF + 2]);
        const float wl = __ldg(&w[t2 / 100 - 1]);     // this lane's row weight

        {
            const float v = (float)t1;
            if (v < 0.0f)         pen = fmaf(v, v, pen);
            else if (v > 1000.0f) { const float u = v - 1000.0f; pen = fmaf(u, u, pen); }
        }

        const float4* in4 = reinterpret_cast<const float4*>(in + base);
        const int4*   tg4 = reinterpret_cast<const int4*>(tg + base);

        // ---- phase A: vectors k=0..2 (6 LDG.128 in flight) ----------------
        float4 xa0 = __ldcs(&in4[0 * 32 + lane]);
        float4 xa1 = __ldcs(&in4[1 * 32 + lane]);
        float4 xa2 = __ldcs(&in4[2 * 32 + lane]);
        int4   ta0 = __ldcs(&tg4[0 * 32 + lane]);
        int4   ta1 = __ldcs(&tg4[1 * 32 + lane]);
        int4   ta2 = __ldcs(&tg4[2 * 32 + lane]);

        proc_vec(xa0, ta0, (unsigned)(0 * 32 + lane) * 4u, wl, acc);
        proc_vec(xa1, ta1, (unsigned)(1 * 32 + lane) * 4u, wl, acc);
        proc_vec(xa2, ta2, (unsigned)(2 * 32 + lane) * 4u, wl, acc);

        // ---- phase B: vectors k=3..5 (k=5 is a 8-lane tail) ---------------
        float4 xb0 = __ldcs(&in4[3 * 32 + lane]);
        float4 xb1 = __ldcs(&in4[4 * 32 + lane]);
        int4   tb0 = __ldcs(&tg4[3 * 32 + lane]);
        int4   tb1 = __ldcs(&tg4[4 * 32 + lane]);

        float4 xb2 = make_float4(0.f, 0.f, 0.f, 0.f);
        int4   tb2 = make_int4(0, 0, 0, 0);
        if (lane < NVEC - 160) {                      // lanes 0..7 carry the tail
            xb2 = __ldcs(&in4[160 + lane]);
            tb2 = __ldcs(&tg4[160 + lane]);
        }

        proc_vec(xb0, tb0, (unsigned)(3 * 32 + lane) * 4u, wl, acc);
        proc_vec(xb1, tb1, (unsigned)(4 * 32 + lane) * 4u, wl, acc);
        proc_vec(xb2, tb2, (unsigned)(5 * 32 + lane) * 4u, wl, acc);
    }

    // ---- warp reduce (fp32), then double across warps ----------------------
    #pragma unroll
    for (int off = 16; off > 0; off >>= 1) {
        acc += __shfl_down_sync(0xFFFFFFFFu, acc, off);
        pen += __shfl_down_sync(0xFFFFFFFFu, pen, off);
    }

    __shared__ float sa[WPB], sp[WPB];
    __shared__ bool  s_last;
    if (lane == 0) { sa[wid] = acc; sp[wid] = pen; }
    __syncthreads();

    if (threadIdx.x == 0) {
        double a = 0.0, p = 0.0;
        #pragma unroll
        for (int i = 0; i < WPB; i++) { a += (double)sa[i]; p += (double)sp[i]; }
        g_pa[blockIdx.x] = a;
        g_pp[blockIdx.x] = p;
        __threadfence();
        const unsigned old = atomicAdd(&g_ctr, 1u);
        s_last = (old == (unsigned)(NB - 1));
    }
    __syncthreads();

    // ---- last-arriving block folds all partials (L2-resident) --------------
    if (s_last) {
        double a = 0.0, p = 0.0;
        for (int i = threadIdx.x; i < NB; i += BDIM) { a += g_pa[i]; p += g_pp[i]; }

        #pragma unroll
        for (int off = 16; off > 0; off >>= 1) {
            a += __shfl_down_sync(0xFFFFFFFFu, a, off);
            p += __shfl_down_sync(0xFFFFFFFFu, p, off);
        }
        __shared__ double da[WPB], dp[WPB];
        if (lane == 0) { da[wid] = a; dp[wid] = p; }
        __syncthreads();
        if (threadIdx.x == 0) {
            double fa = 0.0, fp = 0.0;
            #pragma unroll
            for (int i = 0; i < WPB; i++) { fa += da[i]; fp += dp[i]; }
            out[0] = (float)(fa / ((double)BTOT * (double)NF) + fp);
            g_ctr = 0;   // re-arm for the next graph replay
        }
    }
}

extern "C" void kernel_launch(void* const* d_in, const int* in_sizes, int n_in,
                              void* d_out, int out_size)
{
    const float* in = (const float*)d_in[0];   // inputs  [B, 21] f32
    const int*   tg = (const int*)d_in[1];     // targets [B, 21] i32
    const float* w  = (const float*)d_in[2];   // weights [7]     f32
    float*       out = (float*)d_out;          // scalar  f32

    wmse_fused<<<NB, BDIM>>>(in, tg, w, out);
}